// round 8
// baseline (speedup 1.0000x reference)
#include <cuda_runtime.h>
#include <cstdint>

// ---------------- problem constants (fixed by setup_inputs) ----------------
#define N_NODES 8192
#define DIMS    128
#define KSEL    4096          // N * RATIO
#define NEDGE   8192          // E == N
#define NKEEP   (N_NODES - KSEL)
#define EPSN    1e-12f

// output layout (float32), reference-return order flattened
#define OFF_X     0
#define OFF_EI    (KSEL * DIMS)            // 524288
#define OFF_EJ    (OFF_EI + NKEEP)         // 528384
#define OFF_PERM  (OFF_EJ + NKEEP)         // 532480
#define OFF_BATCH (OFF_PERM + KSEL)        // 536576
#define OFF_W     (OFF_BATCH + KSEL)       // 540672  (total 544768)

// ---------------- device scratch (static, no allocations) ----------------
__device__ float              g_xn[N_NODES * DIMS];   // normalized features (4 MB)
__device__ int                g_deg[N_NODES];
__device__ unsigned int       g_ekeys[NEDGE];         // sorted (src<<13)|dst
__device__ float              g_term[NEDGE];          // per-unique-edge weight term
__device__ float              g_w[N_NODES];
__device__ unsigned long long g_keys[N_NODES];
__device__ int                g_perm[KSEL];
__device__ int                g_newid[N_NODES];
__device__ int                g_sel[N_NODES];

// ---------------- kernels ----------------

// x_norm = x / max(norm, eps). norm computed in double (f32*f32 exact in
// double) -> sqrt -> single rounding to f32 = correctly-rounded norm. The f32
// division then bitwise-matches the reference's elementwise division given the
// same norm. Also clears per-node scratch.
// Warp per row: grid MUST supply 8192 warps = 262144 threads (1024 x 256).
__global__ void k_init(const float* __restrict__ x) {
    int t = blockIdx.x * blockDim.x + threadIdx.x;
    if (t < N_NODES) { g_deg[t] = 0; g_newid[t] = 0; g_sel[t] = 0; }
    int w = t >> 5;                                    // 0..8191 exactly
    int lane = threadIdx.x & 31;
    float4 v = ((const float4*)(x + (size_t)w * DIMS))[lane];
    double s = (double)v.x * v.x + (double)v.y * v.y
             + (double)v.z * v.z + (double)v.w * v.w;
    #pragma unroll
    for (int o = 16; o; o >>= 1) s += __shfl_xor_sync(0xFFFFFFFFu, s, o);
    float nf = fmaxf((float)sqrt(s), EPSN);
    float4 xn;
    xn.x = v.x / nf; xn.y = v.y / nf; xn.z = v.z / nf; xn.w = v.w / nf;
    ((float4*)(g_xn + (size_t)w * DIMS))[lane] = xn;
}

// single-block bitonic ascending sort of edge keys (src<<13)|dst, then
// dedupe-aware degree count (duplicates are adjacent after sorting).
__global__ void k_sortedges(const int* __restrict__ ei) {
    __shared__ unsigned int sk[NEDGE];                 // 32 KB
    int tid = threadIdx.x;
    for (int p = tid; p < NEDGE; p += blockDim.x)
        sk[p] = ((unsigned int)ei[p] << 13) | (unsigned int)ei[NEDGE + p];
    __syncthreads();
    for (int k = 2; k <= NEDGE; k <<= 1) {
        for (int j = k >> 1; j > 0; j >>= 1) {
            for (int p = tid; p < NEDGE; p += blockDim.x) {
                int q = p ^ j;
                if (q > p) {
                    unsigned int a = sk[p], b = sk[q];
                    bool up = ((p & k) == 0);          // ascending block
                    if ((a > b) == up) { sk[p] = b; sk[q] = a; }
                }
            }
            __syncthreads();
        }
    }
    for (int p = tid; p < NEDGE; p += blockDim.x) {
        unsigned int key = sk[p];
        g_ekeys[p] = key;
        if (p == 0 || sk[p - 1] != key)
            atomicAdd(&g_deg[key >> 13], 1);           // unique (i,j) only
    }
}

// per-sorted-edge weight term. warp per position (8192 warps). sim computed as
// double dot of normalized rows (exact products, ~exact sum) rounded once to
// f32; then term = (dis_i * sim) * dis_j matching the reference's elementwise
// multiply order. Duplicate keys emit exact 0.0f.
__global__ void k_term() {
    int p = (blockIdx.x * blockDim.x + threadIdx.x) >> 5;
    int lane = threadIdx.x & 31;
    if (p >= NEDGE) return;
    unsigned int key = g_ekeys[p];
    if (p > 0 && g_ekeys[p - 1] == key) {              // duplicate edge (warp-uniform)
        if (lane == 0) g_term[p] = 0.0f;
        return;
    }
    int i = (int)(key >> 13);
    int j = (int)(key & 8191u);
    float4 a = ((const float4*)(g_xn + (size_t)i * DIMS))[lane];
    float4 b = ((const float4*)(g_xn + (size_t)j * DIMS))[lane];
    double s = (double)a.x * b.x + (double)a.y * b.y
             + (double)a.z * b.z + (double)a.w * b.w;
    #pragma unroll
    for (int o = 16; o; o >>= 1) s += __shfl_xor_sync(0xFFFFFFFFu, s, o);
    if (lane == 0) {
        int dj = g_deg[j];                             // deg[i] >= 1 by construction
        float disi = (float)(1.0 / sqrt((double)g_deg[i]));
        float disj = (dj > 0) ? (float)(1.0 / sqrt((double)dj)) : 0.0f;
        g_term[p] = (disi * (float)s) * disj;
    }
}

// per-node weight: sequential f32 sum of terms in ascending-j order (segment
// of the sorted key array), then build the u64 ranking key.
// weight desc, index asc on ties (matches lax.top_k).
__global__ void k_weights() {
    int i = blockIdx.x * blockDim.x + threadIdx.x;     // node id, grid covers 8192
    unsigned int tlo = (unsigned int)i << 13;
    unsigned int thi = (unsigned int)(i + 1) << 13;
    int lo = 0, hi = NEDGE;
    while (lo < hi) { int m = (lo + hi) >> 1; if (g_ekeys[m] < tlo) lo = m + 1; else hi = m; }
    int seg = lo;
    lo = seg; hi = NEDGE;
    while (lo < hi) { int m = (lo + hi) >> 1; if (g_ekeys[m] < thi) lo = m + 1; else hi = m; }
    float acc = 0.0f;
    for (int p = seg; p < lo; p++) acc += g_term[p];   // ascending j; dups add +0
    g_w[i] = acc;
    unsigned int u = __float_as_uint(acc);
    u = (u & 0x80000000u) ? ~u : (u | 0x80000000u);    // monotone map
    g_keys[i] = ((unsigned long long)u << 32) | (unsigned int)(N_NODES - 1 - i);
}

// single-block bitonic sort, descending, 8192 x u64 in 64KB dynamic smem
__global__ void k_sort() {
    extern __shared__ unsigned long long s[];
    for (int i = threadIdx.x; i < N_NODES; i += blockDim.x) s[i] = g_keys[i];
    __syncthreads();
    for (int k = 2; k <= N_NODES; k <<= 1) {
        for (int j = k >> 1; j > 0; j >>= 1) {
            for (int i = threadIdx.x; i < N_NODES; i += blockDim.x) {
                int ixj = i ^ j;
                if (ixj > i) {
                    unsigned long long a = s[i], b = s[ixj];
                    bool desc = ((i & k) == 0);
                    if ((a < b) == desc) { s[i] = b; s[ixj] = a; }
                }
            }
            __syncthreads();
        }
    }
    for (int i = threadIdx.x; i < N_NODES; i += blockDim.x) g_keys[i] = s[i];
}

// perm / batch_pool / weights outputs + selection flags
__global__ void k_permout(const int* __restrict__ batch, float* __restrict__ out) {
    int k = blockIdx.x * blockDim.x + threadIdx.x;
    if (k >= KSEL) return;
    unsigned long long key = g_keys[k];
    int idx = (N_NODES - 1) - (int)(unsigned int)(key & 0xFFFFFFFFu);
    g_perm[k] = idx;
    g_sel[idx] = 1;
    g_newid[idx] = k;
    out[OFF_PERM + k]  = (float)idx;
    out[OFF_BATCH + k] = (float)batch[idx];
    out[OFF_W + k]     = g_w[idx];
}

// x_pool gather
__global__ void k_xpool(const float* __restrict__ x, float* __restrict__ out) {
    int t = blockIdx.x * blockDim.x + threadIdx.x;
    if (t >= KSEL * DIMS) return;
    int k = t >> 7, d = t & 127;
    out[OFF_X + t] = x[(size_t)g_perm[k] * DIMS + d];
}

// keep = ascending unselected node indices; emit remapped edge endpoints.
// Unselected endpoints map to 0 (g_newid cleared), matching reference new_mask.
__global__ void k_keep(const int* __restrict__ ei, float* __restrict__ out) {
    __shared__ int s_off[1024];
    int tid = threadIdx.x;
    int base = tid * 8;
    int c = 0;
    #pragma unroll
    for (int r = 0; r < 8; r++) c += (g_sel[base + r] == 0);
    s_off[tid] = c;
    __syncthreads();
    for (int o = 1; o < 1024; o <<= 1) {
        int v = s_off[tid];
        int u = (tid >= o) ? s_off[tid - o] : 0;
        __syncthreads();
        s_off[tid] = v + u;
        __syncthreads();
    }
    int off = s_off[tid] - c;   // exclusive prefix
    for (int r = 0; r < 8; r++) {
        int node = base + r;
        if (!g_sel[node]) {
            out[OFF_EI + off] = (float)g_newid[ei[node]];
            out[OFF_EJ + off] = (float)g_newid[ei[NEDGE + node]];
            off++;
        }
    }
}

// ---------------- launch ----------------
extern "C" void kernel_launch(void* const* d_in, const int* in_sizes, int n_in,
                              void* d_out, int out_size) {
    const float* x     = (const float*)d_in[0];
    const int*   ei    = (const int*)d_in[1];     // int32 (confirmed round 5)
    const int*   batch = (const int*)d_in[2];
    float* out = (float*)d_out;

    cudaFuncSetAttribute(k_sort, cudaFuncAttributeMaxDynamicSharedMemorySize,
                         N_NODES * (int)sizeof(unsigned long long));

    k_init     <<<1024, 256>>>(x);               // 262144 threads = 8192 warps (warp/row)
    k_sortedges<<<1, 1024>>>(ei);
    k_term     <<<1024, 256>>>();                // warp per sorted edge
    k_weights  <<<32, 256>>>();
    k_sort     <<<1, 1024, N_NODES * (int)sizeof(unsigned long long)>>>();
    k_permout  <<<16, 256>>>(batch, out);
    k_xpool    <<<2048, 256>>>(x, out);
    k_keep     <<<1, 1024>>>(ei, out);
}

// round 13
// speedup vs baseline: 2.4334x; 2.4334x over previous
#include <cuda_runtime.h>
#include <cstdint>

// ---------------- problem constants (fixed by setup_inputs) ----------------
#define N_NODES 8192
#define DIMS    128
#define KSEL    4096          // N * RATIO
#define NEDGE   8192          // E == N
#define NKEEP   (N_NODES - KSEL)
#define EPSN    1e-12f
#define TILE    2048          // bitonic block tile (4 blocks cover 8192)

// output layout (float32), reference-return order flattened
#define OFF_X     0
#define OFF_EI    (KSEL * DIMS)            // 524288
#define OFF_EJ    (OFF_EI + NKEEP)         // 528384
#define OFF_PERM  (OFF_EJ + NKEEP)         // 532480
#define OFF_BATCH (OFF_PERM + KSEL)        // 536576
#define OFF_W     (OFF_BATCH + KSEL)       // 540672  (total 544768)

// ---------------- device scratch (static, no allocations) ----------------
__device__ float              g_xn[N_NODES * DIMS];   // normalized features (4 MB)
__device__ int                g_deg[N_NODES];
__device__ unsigned int       g_ekeys[NEDGE];         // (src<<13)|dst, sorted asc
__device__ float              g_term[NEDGE];          // per-sorted-edge weight term
__device__ float              g_w[N_NODES];
__device__ unsigned long long g_keys[N_NODES];        // ~rankkey, sorted asc
__device__ int                g_perm[KSEL];
__device__ int                g_newid[N_NODES];
__device__ int                g_sel[N_NODES];
__device__ int                g_segstart[N_NODES];
__device__ int                g_segend[N_NODES];

// ---------------- error-free f32 helpers (FMA pipe only) ----------------
__device__ __forceinline__ void two_sum(float a, float b, float& s, float& e) {
    s = a + b;
    float bp = s - a;
    e = (a - (s - bp)) + (b - bp);
}
__device__ __forceinline__ void acc_prod(float a, float b, float& s, float& c) {
    float p = a * b;
    float e = fmaf(a, b, -p);        // exact product error
    float t, err;
    two_sum(s, p, t, err);
    s = t; c += e + err;
}
__device__ __forceinline__ void merge_sc(float s2, float c2, float& s, float& c) {
    float t, err;
    two_sum(s, s2, t, err);
    s = t; c += c2 + err;
}

// ---------------- kernels ----------------

// clears + initial edge keys + x_norm (compensated f32 dot; one double add+sqrt
// per row for correct rounding). Warp per row: 1024 x 256 = 8192 warps.
__global__ void k_init(const float* __restrict__ x, const int* __restrict__ ei) {
    int t = blockIdx.x * blockDim.x + threadIdx.x;
    if (t < N_NODES) {
        g_deg[t] = 0; g_newid[t] = 0; g_sel[t] = 0; g_segstart[t] = -1;
        g_ekeys[t] = ((unsigned int)ei[t] << 13) | (unsigned int)ei[NEDGE + t];
    }
    int w = t >> 5;
    int lane = threadIdx.x & 31;
    float4 v = ((const float4*)(x + (size_t)w * DIMS))[lane];
    float s = 0.0f, c = 0.0f;
    acc_prod(v.x, v.x, s, c); acc_prod(v.y, v.y, s, c);
    acc_prod(v.z, v.z, s, c); acc_prod(v.w, v.w, s, c);
    #pragma unroll
    for (int o = 16; o; o >>= 1) {
        float s2 = __shfl_xor_sync(0xFFFFFFFFu, s, o);
        float c2 = __shfl_xor_sync(0xFFFFFFFFu, c, o);
        merge_sc(s2, c2, s, c);
    }
    float nf = fmaxf((float)sqrt((double)s + (double)c), EPSN);
    float4 xn;
    xn.x = v.x / nf; xn.y = v.y / nf; xn.z = v.z / nf; xn.w = v.w / nf;
    ((float4*)(g_xn + (size_t)w * DIMS))[lane] = xn;
}

// ---- multi-block bitonic sort (ascending), 4 blocks x 2048-element tiles ----
// edge keys (u32)
__global__ void ke_full() {
    __shared__ unsigned int s[TILE];
    int t = threadIdx.x, base = blockIdx.x * TILE;
    s[t] = g_ekeys[base + t]; s[t + 1024] = g_ekeys[base + t + 1024];
    __syncthreads();
    for (int k = 2; k <= TILE; k <<= 1)
        for (int j = k >> 1; j > 0; j >>= 1) {
            int lo = t & (j - 1);
            int il = ((t & ~(j - 1)) << 1) | lo;
            int pr = il | j;
            bool up = (((base + il) & k) == 0);
            unsigned int a = s[il], b = s[pr];
            if ((a > b) == up) { s[il] = b; s[pr] = a; }
            __syncthreads();
        }
    g_ekeys[base + t] = s[t]; g_ekeys[base + t + 1024] = s[t + 1024];
}
__global__ void ke_g(int k, int j) {
    int t = blockIdx.x * blockDim.x + threadIdx.x;   // 4096 threads
    int lo = t & (j - 1);
    int i = ((t & ~(j - 1)) << 1) | lo;
    int pr = i | j;
    bool up = ((i & k) == 0);
    unsigned int a = g_ekeys[i], b = g_ekeys[pr];
    if ((a > b) == up) { g_ekeys[i] = b; g_ekeys[pr] = a; }
}
__global__ void ke_fin(int k) {
    __shared__ unsigned int s[TILE];
    int t = threadIdx.x, base = blockIdx.x * TILE;
    s[t] = g_ekeys[base + t]; s[t + 1024] = g_ekeys[base + t + 1024];
    __syncthreads();
    for (int j = TILE >> 1; j > 0; j >>= 1) {
        int lo = t & (j - 1);
        int il = ((t & ~(j - 1)) << 1) | lo;
        int pr = il | j;
        bool up = (((base + il) & k) == 0);
        unsigned int a = s[il], b = s[pr];
        if ((a > b) == up) { s[il] = b; s[pr] = a; }
        __syncthreads();
    }
    g_ekeys[base + t] = s[t]; g_ekeys[base + t + 1024] = s[t + 1024];
}
// weight rank keys (u64)
__global__ void kw_full() {
    __shared__ unsigned long long s[TILE];
    int t = threadIdx.x, base = blockIdx.x * TILE;
    s[t] = g_keys[base + t]; s[t + 1024] = g_keys[base + t + 1024];
    __syncthreads();
    for (int k = 2; k <= TILE; k <<= 1)
        for (int j = k >> 1; j > 0; j >>= 1) {
            int lo = t & (j - 1);
            int il = ((t & ~(j - 1)) << 1) | lo;
            int pr = il | j;
            bool up = (((base + il) & k) == 0);
            unsigned long long a = s[il], b = s[pr];
            if ((a > b) == up) { s[il] = b; s[pr] = a; }
            __syncthreads();
        }
    g_keys[base + t] = s[t]; g_keys[base + t + 1024] = s[t + 1024];
}
__global__ void kw_g(int k, int j) {
    int t = blockIdx.x * blockDim.x + threadIdx.x;   // 4096 threads
    int lo = t & (j - 1);
    int i = ((t & ~(j - 1)) << 1) | lo;
    int pr = i | j;
    bool up = ((i & k) == 0);
    unsigned long long a = g_keys[i], b = g_keys[pr];
    if ((a > b) == up) { g_keys[i] = b; g_keys[pr] = a; }
}
__global__ void kw_fin(int k) {
    __shared__ unsigned long long s[TILE];
    int t = threadIdx.x, base = blockIdx.x * TILE;
    s[t] = g_keys[base + t]; s[t + 1024] = g_keys[base + t + 1024];
    __syncthreads();
    for (int j = TILE >> 1; j > 0; j >>= 1) {
        int lo = t & (j - 1);
        int il = ((t & ~(j - 1)) << 1) | lo;
        int pr = il | j;
        bool up = (((base + il) & k) == 0);
        unsigned long long a = s[il], b = s[pr];
        if ((a > b) == up) { s[il] = b; s[pr] = a; }
        __syncthreads();
    }
    g_keys[base + t] = s[t]; g_keys[base + t + 1024] = s[t + 1024];
}

// degree (unique edges only; duplicates adjacent after sort) + segment bounds
__global__ void k_deg() {
    int p = blockIdx.x * blockDim.x + threadIdx.x;   // 8192
    unsigned int key = g_ekeys[p];
    int src = (int)(key >> 13);
    unsigned int prev = (p > 0) ? g_ekeys[p - 1] : 0xFFFFFFFFu;
    if (p == 0 || (int)(prev >> 13) != src) g_segstart[src] = p;
    if (p == NEDGE - 1 || (int)(g_ekeys[p + 1] >> 13) != src) g_segend[src] = p + 1;
    if (p == 0 || prev != key) atomicAdd(&g_deg[src], 1);
}

// per-sorted-edge weight term: compensated f32 dot of normalized rows, rounded
// once via double; term = (dis_i * sim) * dis_j (reference multiply order).
// Duplicate keys emit exact +0.0f. Warp per edge (8192 warps).
__global__ void k_term() {
    int p = (blockIdx.x * blockDim.x + threadIdx.x) >> 5;
    int lane = threadIdx.x & 31;
    unsigned int key = g_ekeys[p];
    if (p > 0 && g_ekeys[p - 1] == key) {            // duplicate (warp-uniform)
        if (lane == 0) g_term[p] = 0.0f;
        return;
    }
    int i = (int)(key >> 13);
    int j = (int)(key & 8191u);
    float4 a = ((const float4*)(g_xn + (size_t)i * DIMS))[lane];
    float4 b = ((const float4*)(g_xn + (size_t)j * DIMS))[lane];
    float s = 0.0f, c = 0.0f;
    acc_prod(a.x, b.x, s, c); acc_prod(a.y, b.y, s, c);
    acc_prod(a.z, b.z, s, c); acc_prod(a.w, b.w, s, c);
    #pragma unroll
    for (int o = 16; o; o >>= 1) {
        float s2 = __shfl_xor_sync(0xFFFFFFFFu, s, o);
        float c2 = __shfl_xor_sync(0xFFFFFFFFu, c, o);
        merge_sc(s2, c2, s, c);
    }
    if (lane == 0) {
        float sim = (float)((double)s + (double)c);
        int dj = g_deg[j];
        float disi = (float)(1.0 / sqrt((double)g_deg[i]));
        float disj = (dj > 0) ? (float)(1.0 / sqrt((double)dj)) : 0.0f;
        g_term[p] = (disi * sim) * disj;
    }
}

// per-node weight: sequential f32 sum over precomputed segment (ascending j,
// matching reference sum order), then inverted u64 rank key (ascending sort of
// ~key == descending weight, index-ascending ties -> matches lax.top_k).
__global__ void k_weights() {
    int i = blockIdx.x * blockDim.x + threadIdx.x;   // 8192
    float acc = 0.0f;
    int s0 = g_segstart[i];
    if (s0 >= 0) {
        int s1 = g_segend[i];
        for (int p = s0; p < s1; p++) acc += g_term[p];
    }
    g_w[i] = acc;
    unsigned int u = __float_as_uint(acc);
    u = (u & 0x80000000u) ? ~u : (u | 0x80000000u);  // monotone map
    g_keys[i] = ~(((unsigned long long)u << 32) | (unsigned int)(N_NODES - 1 - i));
}

// perm / batch_pool / weights outputs + selection flags
__global__ void k_permout(const int* __restrict__ batch, float* __restrict__ out) {
    int k = blockIdx.x * blockDim.x + threadIdx.x;
    if (k >= KSEL) return;
    unsigned long long key = ~g_keys[k];             // undo inversion
    int idx = (N_NODES - 1) - (int)(unsigned int)(key & 0xFFFFFFFFu);
    g_perm[k] = idx;
    g_sel[idx] = 1;
    g_newid[idx] = k;
    out[OFF_PERM + k]  = (float)idx;
    out[OFF_BATCH + k] = (float)batch[idx];
    out[OFF_W + k]     = g_w[idx];
}

// x_pool gather
__global__ void k_xpool(const float* __restrict__ x, float* __restrict__ out) {
    int t = blockIdx.x * blockDim.x + threadIdx.x;
    if (t >= KSEL * DIMS) return;
    int k = t >> 7, d = t & 127;
    out[OFF_X + t] = x[(size_t)g_perm[k] * DIMS + d];
}

// keep = ascending unselected node indices; emit remapped edge endpoints.
__global__ void k_keep(const int* __restrict__ ei, float* __restrict__ out) {
    __shared__ int s_off[1024];
    int tid = threadIdx.x;
    int base = tid * 8;
    int c = 0;
    #pragma unroll
    for (int r = 0; r < 8; r++) c += (g_sel[base + r] == 0);
    s_off[tid] = c;
    __syncthreads();
    for (int o = 1; o < 1024; o <<= 1) {
        int v = s_off[tid];
        int u = (tid >= o) ? s_off[tid - o] : 0;
        __syncthreads();
        s_off[tid] = v + u;
        __syncthreads();
    }
    int off = s_off[tid] - c;   // exclusive prefix
    for (int r = 0; r < 8; r++) {
        int node = base + r;
        if (!g_sel[node]) {
            out[OFF_EI + off] = (float)g_newid[ei[node]];
            out[OFF_EJ + off] = (float)g_newid[ei[NEDGE + node]];
            off++;
        }
    }
}

// ---------------- launch ----------------
extern "C" void kernel_launch(void* const* d_in, const int* in_sizes, int n_in,
                              void* d_out, int out_size) {
    const float* x     = (const float*)d_in[0];
    const int*   ei    = (const int*)d_in[1];     // int32 (confirmed round 5)
    const int*   batch = (const int*)d_in[2];
    float* out = (float*)d_out;

    k_init   <<<1024, 256>>>(x, ei);              // 8192 warps (warp/row) + edge keys

    ke_full  <<<4, 1024>>>();                     // edge sort: k=2..2048 block-local
    ke_g     <<<16, 256>>>(4096, 2048);
    ke_fin   <<<4, 1024>>>(4096);
    ke_g     <<<16, 256>>>(8192, 4096);
    ke_g     <<<16, 256>>>(8192, 2048);
    ke_fin   <<<4, 1024>>>(8192);

    k_deg    <<<32, 256>>>();
    k_term   <<<1024, 256>>>();                   // warp per sorted edge
    k_weights<<<32, 256>>>();

    kw_full  <<<4, 1024>>>();                     // rank sort (ascending on ~key)
    kw_g     <<<16, 256>>>(4096, 2048);
    kw_fin   <<<4, 1024>>>(4096);
    kw_g     <<<16, 256>>>(8192, 4096);
    kw_g     <<<16, 256>>>(8192, 2048);
    kw_fin   <<<4, 1024>>>(8192);

    k_permout<<<16, 256>>>(batch, out);
    k_xpool  <<<2048, 256>>>(x, out);
    k_keep   <<<1, 1024>>>(ei, out);
}